// round 15
// baseline (speedup 1.0000x reference)
#include <cuda_runtime.h>
#include <cuda_bf16.h>
#include <cuda_fp16.h>
#include <math.h>

// Problem constants (GCN_83081847374393)
#define N_SRC0   50000
#define N_DST0V  20000
#define N_DST1   5000
#define VOCAB    50000
#define EMB      128
#define HID      256
#define OUTD     16
#define WORDS_PER_NODE 50   // (10 * 5)
#define ST0      128        // ELL stride layer 0 (Poisson mean 15 -> 128 is >>8 sigma)
#define ST1      128        // ELL stride layer 1 (mean 15)

// -------- scratch (device globals; no allocation allowed) --------
__device__ __align__(16) __half g_t16[(size_t)VOCAB  * EMB];   // 12.8 MB fp16 word table
__device__ __align__(16) __half g_w1t[(size_t)HID * EMB];      // 64 KB   fp16 W1^T [N][K]
__device__ __align__(16) __half g_x16[(size_t)N_SRC0 * EMB];   // 12.8 MB fp16 scaled embeddings
__device__ __align__(16) __half g_h16[(size_t)N_DST0V * HID];  // 10.2 MB fp16 scaled layer-1 out
__device__ int   g_deg_out0[N_SRC0];
__device__ int   g_deg_out1[N_DST0V];
__device__ int   g_cnt0[N_DST0V];                // doubles as deg_in0
__device__ int   g_cnt1[N_DST1];                 // doubles as deg_in1
__device__ int   g_csr0[(size_t)N_DST0V * ST0];  // ELL buckets: src ids per dst
__device__ int   g_csr1[(size_t)N_DST1  * ST1];

// ---------------- init: fp16 table + fp16 W1^T + zero counters ----------------
__global__ void k_init(const float* __restrict__ table, const float* __restrict__ W1) {
    int t = blockIdx.x * blockDim.x + threadIdx.x;
    size_t i = (size_t)t * 4;
    if (i < (size_t)VOCAB * EMB) {
        float4 v = *(const float4*)(table + i);
        __half2 h0 = __floats2half2_rn(v.x, v.y);
        __half2 h1 = __floats2half2_rn(v.z, v.w);
        uint2 o; o.x = *(unsigned*)&h0; o.y = *(unsigned*)&h1;
        *(uint2*)(g_t16 + i) = o;
    }
    if (t < HID * EMB) {                          // W1t[n][k] = W1[k][n]
        int n = t >> 7, k = t & 127;
        g_w1t[t] = __float2half(W1[(size_t)k * HID + n]);
    }
    if (t < N_SRC0)  g_deg_out0[t] = 0;
    if (t < N_DST0V) { g_deg_out1[t] = 0; g_cnt0[t] = 0; }
    if (t < N_DST1)  g_cnt1[t] = 0;
}

// ---------------- single edge pass: out-degrees + ELL bucket fill ----------------
__global__ void k_prep(const int* __restrict__ src0, const int* __restrict__ dst0, int e0,
                       const int* __restrict__ src1, const int* __restrict__ dst1, int e1) {
    int base = (blockIdx.x * blockDim.x + threadIdx.x) * 4;
#pragma unroll
    for (int k = 0; k < 4; k++) {
        int i = base + k;
        if (i < e0) {
            int s = src0[i], d = dst0[i];
            atomicAdd(&g_deg_out0[s], 1);
            int p = atomicAdd(&g_cnt0[d], 1);
            if (p < ST0) g_csr0[(size_t)d * ST0 + p] = s;
        }
        if (i < e1) {
            int s = src1[i], d = dst1[i];
            atomicAdd(&g_deg_out1[s], 1);
            int p = atomicAdd(&g_cnt1[d], 1);
            if (p < ST1) g_csr1[(size_t)d * ST1 + p] = s;
        }
    }
}

// ---------------- embedding gather (fp16 table) + mean + deg_out0 scale -> fp16 ----
__global__ void k_embed(const int* __restrict__ uw, int n_nodes) {
    int warp = (blockIdx.x * blockDim.x + threadIdx.x) >> 5;
    int lane = threadIdx.x & 31;
    if (warp >= n_nodes) return;
    const int* w = uw + (size_t)warp * WORDS_PER_NODE;
    float ax = 0.f, ay = 0.f, az = 0.f, aw = 0.f;
#pragma unroll 5
    for (int j = 0; j < WORDS_PER_NODE; j++) {
        int idx = __ldg(&w[j]);                          // warp-uniform -> broadcast
        uint2 p = *(const uint2*)(g_t16 + (size_t)idx * EMB + lane * 4);
        float2 f0 = __half22float2(*(__half2*)&p.x);
        float2 f1 = __half22float2(*(__half2*)&p.y);
        ax += f0.x; ay += f0.y; az += f1.x; aw += f1.y;
    }
    float sc = rsqrtf(fmaxf((float)g_deg_out0[warp], 1.0f)) * (1.0f / WORDS_PER_NODE);
    __half2 h0 = __floats2half2_rn(ax * sc, ay * sc);
    __half2 h1 = __floats2half2_rn(az * sc, aw * sc);
    uint2 o; o.x = *(unsigned*)&h0; o.y = *(unsigned*)&h1;
    *(uint2*)(g_x16 + (size_t)warp * EMB + lane * 4) = o;
}

// ---------------- fused gather + HMMA GEMM1 ----------------
// h1 = relu( (sum ELL0) * rsqrt(deg_in0) @ W1 + b1 ) * rsqrt(deg_out1)
// 32 rows/block, 8 warps. Gather: 4 rows concurrent per warp (4 indep chains),
// sentinel indices, fp16 HADD2 accum.
#define TILE_R1 32
__global__ void __launch_bounds__(256) k_gemm1(const float* __restrict__ b1) {
    __shared__ __half s_a[TILE_R1][EMB + 8];   // +8 pad: break 256B-stride bank collision
    __shared__ float s_sout[TILE_R1];
    int tid  = threadIdx.x;
    int wid  = tid >> 5;
    int lane = tid & 31;
    int row0 = blockIdx.x * TILE_R1;

    {
        const __half2 zero2 = __float2half2_rn(0.0f);
        int   deg[4], dc[4];
        const int* bkt[4];
        __half2 acc[4][2];
#pragma unroll
        for (int q = 0; q < 4; q++) {
            int r = wid + q * 8;
            deg[q] = g_cnt0[row0 + r];
            dc[q]  = deg[q] < ST0 ? deg[q] : ST0;
            bkt[q] = g_csr0 + (size_t)(row0 + r) * ST0;
            acc[q][0] = zero2; acc[q][1] = zero2;
        }
        int dmax = dc[0];
#pragma unroll
        for (int q = 1; q < 4; q++) dmax = dc[q] > dmax ? dc[q] : dmax;

        for (int j0 = 0; j0 < dmax; j0 += 32) {
            int idx[4];
#pragma unroll
            for (int q = 0; q < 4; q++)
                idx[q] = (j0 + lane < dc[q]) ? bkt[q][j0 + lane] : -1;
            int m = dmax - j0; if (m > 32) m = 32;
#pragma unroll 4
            for (int jj = 0; jj < m; jj++) {
#pragma unroll
                for (int q = 0; q < 4; q++) {
                    int s = __shfl_sync(0xffffffffu, idx[q], jj);
                    if (s >= 0) {
                        uint2 p = *(const uint2*)(g_x16 + (size_t)s * EMB + lane * 4);
                        acc[q][0] = __hadd2(acc[q][0], *(__half2*)&p.x);
                        acc[q][1] = __hadd2(acc[q][1], *(__half2*)&p.y);
                    }
                }
            }
        }
#pragma unroll
        for (int q = 0; q < 4; q++) {
            int r = wid + q * 8;
            float sc = rsqrtf(fmaxf((float)deg[q], 1.0f));
            float2 f0 = __half22float2(acc[q][0]);
            float2 f1 = __half22float2(acc[q][1]);
            *(__half2*)&s_a[r][lane * 4]     = __floats2half2_rn(f0.x * sc, f0.y * sc);
            *(__half2*)&s_a[r][lane * 4 + 2] = __floats2half2_rn(f1.x * sc, f1.y * sc);
        }
    }
    if (tid < TILE_R1) s_sout[tid] = rsqrtf(fmaxf((float)g_deg_out1[row0 + tid], 1.0f));
    __syncthreads();

    // HMMA phase: m16n8k16.f32.f16.f16.f32, 2 m-tiles x 4 n-tiles per warp
    int n0 = wid * 32;
    int qr = lane >> 2;        // t/4
    int qc = (lane & 3) * 2;   // (t%4)*2
    float c[2][4][4];
#pragma unroll
    for (int m = 0; m < 2; m++)
#pragma unroll
        for (int nt = 0; nt < 4; nt++)
#pragma unroll
            for (int x = 0; x < 4; x++) c[m][nt][x] = 0.0f;

#pragma unroll
    for (int ks = 0; ks < 8; ks++) {
        int k0 = ks * 16;
        unsigned a[2][4];
#pragma unroll
        for (int m = 0; m < 2; m++) {
            int mr = m * 16 + qr;
            a[m][0] = *(const unsigned*)&s_a[mr][k0 + qc];
            a[m][1] = *(const unsigned*)&s_a[mr + 8][k0 + qc];
            a[m][2] = *(const unsigned*)&s_a[mr][k0 + qc + 8];
            a[m][3] = *(const unsigned*)&s_a[mr + 8][k0 + qc + 8];
        }
#pragma unroll
        for (int nt = 0; nt < 4; nt++) {
            int n = n0 + nt * 8 + qr;
            unsigned bb0 = *(const unsigned*)(g_w1t + (size_t)n * EMB + k0 + qc);
            unsigned bb1 = *(const unsigned*)(g_w1t + (size_t)n * EMB + k0 + qc + 8);
#pragma unroll
            for (int m = 0; m < 2; m++) {
                asm volatile(
                    "mma.sync.aligned.m16n8k16.row.col.f32.f16.f16.f32 "
                    "{%0,%1,%2,%3}, {%4,%5,%6,%7}, {%8,%9}, {%0,%1,%2,%3};"
                    : "+f"(c[m][nt][0]), "+f"(c[m][nt][1]),
                      "+f"(c[m][nt][2]), "+f"(c[m][nt][3])
                    : "r"(a[m][0]), "r"(a[m][1]), "r"(a[m][2]), "r"(a[m][3]),
                      "r"(bb0), "r"(bb1));
            }
        }
    }

    // epilogue: +bias, relu, *rsqrt(deg_out1), fp16 stores (half2 pairs)
#pragma unroll
    for (int nt = 0; nt < 4; nt++) {
        int col = n0 + nt * 8 + qc;
        float bc0 = b1[col], bc1 = b1[col + 1];
#pragma unroll
        for (int m = 0; m < 2; m++) {
            int rlo = m * 16 + qr, rhi = rlo + 8;
            float s0 = s_sout[rlo], s1 = s_sout[rhi];
            __half2 vlo = __floats2half2_rn(fmaxf(c[m][nt][0] + bc0, 0.0f) * s0,
                                            fmaxf(c[m][nt][1] + bc1, 0.0f) * s0);
            __half2 vhi = __floats2half2_rn(fmaxf(c[m][nt][2] + bc0, 0.0f) * s1,
                                            fmaxf(c[m][nt][3] + bc1, 0.0f) * s1);
            *(__half2*)&g_h16[(size_t)(row0 + rlo) * HID + col] = vlo;
            *(__half2*)&g_h16[(size_t)(row0 + rhi) * HID + col] = vhi;
        }
    }
}

// ---------------- fused gather + GEMM2 -> d_out ----------------
// 16 rows/block, 8 warps. Gather: 2 rows per warp, sentinel indices, HADD2 accum.
__global__ void __launch_bounds__(256) k_gemm2(const float* __restrict__ W2,
                                               const float* __restrict__ b2,
                                               float* __restrict__ out, int n_rows) {
    __shared__ float s_w[HID * OUTD];   // 16 KB
    __shared__ float s_a[16][HID];      // 16 KB
    int tid  = threadIdx.x;
    int wid  = tid >> 5;
    int lane = tid & 31;
    int row0 = blockIdx.x * 16;

#pragma unroll
    for (int i = tid; i < HID * OUTD; i += 256) s_w[i] = W2[i];

    {
        const __half2 zero2 = __float2half2_rn(0.0f);
        int   deg[2], dc[2];
        const int* bkt[2];
        __half2 acc[2][4];
#pragma unroll
        for (int q = 0; q < 2; q++) {
            int row = row0 + wid + q * 8;
            bool ok = row < n_rows;
            deg[q] = ok ? g_cnt1[row] : 0;
            dc[q]  = deg[q] < ST1 ? deg[q] : ST1;
            bkt[q] = g_csr1 + (size_t)row * ST1;
            acc[q][0] = zero2; acc[q][1] = zero2; acc[q][2] = zero2; acc[q][3] = zero2;
        }
        int dmax = dc[0] > dc[1] ? dc[0] : dc[1];

        for (int j0 = 0; j0 < dmax; j0 += 32) {
            int idx[2];
#pragma unroll
            for (int q = 0; q < 2; q++)
                idx[q] = (j0 + lane < dc[q]) ? bkt[q][j0 + lane] : -1;
            int m = dmax - j0; if (m > 32) m = 32;
#pragma unroll 4
            for (int jj = 0; jj < m; jj++) {
#pragma unroll
                for (int q = 0; q < 2; q++) {
                    int s = __shfl_sync(0xffffffffu, idx[q], jj);
                    if (s >= 0) {
                        uint4 p = *(const uint4*)(g_h16 + (size_t)s * HID + lane * 8);
                        acc[q][0] = __hadd2(acc[q][0], *(__half2*)&p.x);
                        acc[q][1] = __hadd2(acc[q][1], *(__half2*)&p.y);
                        acc[q][2] = __hadd2(acc[q][2], *(__half2*)&p.z);
                        acc[q][3] = __hadd2(acc[q][3], *(__half2*)&p.w);
                    }
                }
            }
        }
#pragma unroll
        for (int q = 0; q < 2; q++) {
            int r = wid + q * 8;
            float sc = rsqrtf(fmaxf((float)deg[q], 1.0f));
#pragma unroll
            for (int h = 0; h < 4; h++) {
                float2 f = __half22float2(acc[q][h]);
                float2 o; o.x = f.x * sc; o.y = f.y * sc;
                *(float2*)&s_a[r][lane * 8 + h * 2] = o;
            }
        }
    }
    __syncthreads();

    int r_local = tid >> 4;
    int c       = tid & 15;
    int row     = row0 + r_local;
    if (row >= n_rows) return;

    float acc = 0.0f;
#pragma unroll 8
    for (int k4 = 0; k4 < HID / 4; k4++) {
        float4 av = *(const float4*)&s_a[r_local][k4 * 4];
        acc = fmaf(av.x, s_w[(k4 * 4 + 0) * OUTD + c], acc);
        acc = fmaf(av.y, s_w[(k4 * 4 + 1) * OUTD + c], acc);
        acc = fmaf(av.z, s_w[(k4 * 4 + 2) * OUTD + c], acc);
        acc = fmaf(av.w, s_w[(k4 * 4 + 3) * OUTD + c], acc);
    }
    out[(size_t)row * OUTD + c] = fmaxf(acc + b2[c], 0.0f);
}

// ---------------- labels tail: cast int labels to float ----------------
__global__ void k_labels(const int* __restrict__ labels, float* __restrict__ out,
                         int offset, int n) {
    int i = blockIdx.x * blockDim.x + threadIdx.x;
    if (i < n) out[offset + i] = (float)labels[i];
}

extern "C" void kernel_launch(void* const* d_in, const int* in_sizes, int n_in,
                              void* d_out, int out_size) {
    const int*   user_word = (const int*)  d_in[0];
    const int*   labels    = (const int*)  d_in[1];
    const int*   src0      = (const int*)  d_in[2];
    const int*   dst0      = (const int*)  d_in[3];
    const int*   src1      = (const int*)  d_in[4];
    const int*   dst1      = (const int*)  d_in[5];
    const float* table     = (const float*)d_in[6];
    const float* W1        = (const float*)d_in[7];
    const float* b1        = (const float*)d_in[8];
    const float* W2        = (const float*)d_in[9];
    const float* b2        = (const float*)d_in[10];
    float* out = (float*)d_out;

    const int n_nodes = in_sizes[0] / WORDS_PER_NODE;  // 50000
    const int n_dst1  = in_sizes[1];                   // 5000
    const int e0      = in_sizes[2];                   // 300000
    const int e1      = in_sizes[4];                   // 75000

    // 1. init: fp16 table + fp16 W1^T + zero counters
    {
        size_t n4 = ((size_t)VOCAB * EMB) / 4;
        k_init<<<(unsigned)((n4 + 255) / 256), 256>>>(table, W1);
    }
    // 2. single edge pass: out-degrees + ELL buckets (cnt == in-degree)
    {
        int n = e0 > e1 ? e0 : e1;
        k_prep<<<(n + 1023) / 1024, 256>>>(src0, dst0, e0, src1, dst1, e1);
    }
    // 3. embedding gather/mean from fp16 table (+deg_out0 scale) -> fp16 x
    k_embed<<<(n_nodes * 32 + 255) / 256, 256>>>(user_word, n_nodes);
    // 4. fused gather + HMMA GEMM1 -> fp16 h1
    k_gemm1<<<N_DST0V / TILE_R1, 256>>>(b1);
    // 5. fused gather + GEMM2 -> d_out head
    k_gemm2<<<(n_dst1 + 15) / 16, 256>>>(W2, b2, out, n_dst1);
    // 6. labels tail (as float)
    int feat = n_dst1 * OUTD;
    int nlab = out_size - feat;
    if (nlab > 0) {
        if (nlab > n_dst1) nlab = n_dst1;
        k_labels<<<(nlab + 255) / 256, 256>>>(labels, out, feat, nlab);
    }
}

// round 17
// speedup vs baseline: 1.0320x; 1.0320x over previous
#include <cuda_runtime.h>
#include <cuda_bf16.h>
#include <cuda_fp16.h>
#include <math.h>

// Problem constants (GCN_83081847374393)
#define N_SRC0   50000
#define N_DST0V  20000
#define N_DST1   5000
#define VOCAB    50000
#define EMB      128
#define HID      256
#define OUTD     16
#define WORDS_PER_NODE 50   // (10 * 5)
#define ST0      128        // ELL stride layer 0
#define ST1      128        // ELL stride layer 1

// -------- scratch (device globals; no allocation allowed) --------
__device__ __align__(16) __half g_t16[(size_t)VOCAB  * EMB];   // 12.8 MB fp16 word table
__device__ __align__(16) __half g_w1t[(size_t)HID * EMB];      // 64 KB   fp16 W1^T [N][K]
__device__ __align__(16) __half g_x16[(size_t)N_SRC0 * EMB];   // 12.8 MB fp16 scaled embeddings
__device__ __align__(16) __half g_a0 [(size_t)N_DST0V * EMB];  // 5.1 MB  fp16 gathered+scaled A (layer1)
__device__ __align__(16) __half g_h16[(size_t)N_DST0V * HID];  // 10.2 MB fp16 scaled layer-1 out
__device__ __align__(16) float  g_a1 [(size_t)N_DST1 * HID];   // 5.1 MB  fp32 gathered+scaled A (layer2)
__device__ int   g_deg_out0[N_SRC0];
__device__ int   g_deg_out1[N_DST0V];
__device__ int   g_cnt0[N_DST0V];                // doubles as deg_in0
__device__ int   g_cnt1[N_DST1];                 // doubles as deg_in1
__device__ int   g_csr0[(size_t)N_DST0V * ST0];  // ELL buckets: src ids per dst
__device__ int   g_csr1[(size_t)N_DST1  * ST1];

// ---------------- init: fp16 table + fp16 W1^T + zero counters ----------------
__global__ void k_init(const float* __restrict__ table, const float* __restrict__ W1) {
    int t = blockIdx.x * blockDim.x + threadIdx.x;
    size_t i = (size_t)t * 4;
    if (i < (size_t)VOCAB * EMB) {
        float4 v = *(const float4*)(table + i);
        __half2 h0 = __floats2half2_rn(v.x, v.y);
        __half2 h1 = __floats2half2_rn(v.z, v.w);
        uint2 o; o.x = *(unsigned*)&h0; o.y = *(unsigned*)&h1;
        *(uint2*)(g_t16 + i) = o;
    }
    if (t < HID * EMB) {                          // W1t[n][k] = W1[k][n]
        int n = t >> 7, k = t & 127;
        g_w1t[t] = __float2half(W1[(size_t)k * HID + n]);
    }
    if (t < N_SRC0)  g_deg_out0[t] = 0;
    if (t < N_DST0V) { g_deg_out1[t] = 0; g_cnt0[t] = 0; }
    if (t < N_DST1)  g_cnt1[t] = 0;
}

// ---------------- single edge pass: out-degrees + ELL bucket fill ----------------
__global__ void k_prep(const int* __restrict__ src0, const int* __restrict__ dst0, int e0,
                       const int* __restrict__ src1, const int* __restrict__ dst1, int e1) {
    int base = (blockIdx.x * blockDim.x + threadIdx.x) * 4;
#pragma unroll
    for (int k = 0; k < 4; k++) {
        int i = base + k;
        if (i < e0) {
            int s = src0[i], d = dst0[i];
            atomicAdd(&g_deg_out0[s], 1);
            int p = atomicAdd(&g_cnt0[d], 1);
            if (p < ST0) g_csr0[(size_t)d * ST0 + p] = s;
        }
        if (i < e1) {
            int s = src1[i], d = dst1[i];
            atomicAdd(&g_deg_out1[s], 1);
            int p = atomicAdd(&g_cnt1[d], 1);
            if (p < ST1) g_csr1[(size_t)d * ST1 + p] = s;
        }
    }
}

// ---------------- embedding gather (fp16 table) + mean + deg_out0 scale -> fp16 ----
__global__ void k_embed(const int* __restrict__ uw, int n_nodes) {
    int warp = (blockIdx.x * blockDim.x + threadIdx.x) >> 5;
    int lane = threadIdx.x & 31;
    if (warp >= n_nodes) return;
    const int* w = uw + (size_t)warp * WORDS_PER_NODE;
    float ax = 0.f, ay = 0.f, az = 0.f, aw = 0.f;
#pragma unroll 5
    for (int j = 0; j < WORDS_PER_NODE; j++) {
        int idx = __ldg(&w[j]);                          // warp-uniform -> broadcast
        uint2 p = *(const uint2*)(g_t16 + (size_t)idx * EMB + lane * 4);
        float2 f0 = __half22float2(*(__half2*)&p.x);
        float2 f1 = __half22float2(*(__half2*)&p.y);
        ax += f0.x; ay += f0.y; az += f1.x; aw += f1.y;
    }
    float sc = rsqrtf(fmaxf((float)g_deg_out0[warp], 1.0f)) * (1.0f / WORDS_PER_NODE);
    __half2 h0 = __floats2half2_rn(ax * sc, ay * sc);
    __half2 h1 = __floats2half2_rn(az * sc, aw * sc);
    uint2 o; o.x = *(unsigned*)&h0; o.y = *(unsigned*)&h1;
    *(uint2*)(g_x16 + (size_t)warp * EMB + lane * 4) = o;
}

// ---------------- layer-1 neighbor gather: one warp per dst row ----------------
// g_a0[row] = (sum_{s in ELL0[row]} x16[s]) * rsqrt(deg_in0[row])   (fp16)
__global__ void k_gather0() {
    int warp = (blockIdx.x * blockDim.x + threadIdx.x) >> 5;
    int lane = threadIdx.x & 31;
    if (warp >= N_DST0V) return;
    int deg = g_cnt0[warp];
    int dc  = deg < ST0 ? deg : ST0;
    const int* bkt = g_csr0 + (size_t)warp * ST0;
    const __half2 zero2 = __float2half2_rn(0.0f);
    __half2 a0 = zero2, a1 = zero2;
    for (int j0 = 0; j0 < dc; j0 += 32) {
        int idx = (j0 + lane < dc) ? bkt[j0 + lane] : -1;
        int m = dc - j0; if (m > 32) m = 32;
#pragma unroll 8
        for (int jj = 0; jj < m; jj++) {
            int s = __shfl_sync(0xffffffffu, idx, jj);
            uint2 p = *(const uint2*)(g_x16 + (size_t)s * EMB + lane * 4);
            a0 = __hadd2(a0, *(__half2*)&p.x);
            a1 = __hadd2(a1, *(__half2*)&p.y);
        }
    }
    float sc = rsqrtf(fmaxf((float)deg, 1.0f));
    float2 f0 = __half22float2(a0), f1 = __half22float2(a1);
    __half2 o0 = __floats2half2_rn(f0.x * sc, f0.y * sc);
    __half2 o1 = __floats2half2_rn(f1.x * sc, f1.y * sc);
    uint2 o; o.x = *(unsigned*)&o0; o.y = *(unsigned*)&o1;
    *(uint2*)(g_a0 + (size_t)warp * EMB + lane * 4) = o;
}

// ---------------- dense HMMA GEMM1: h1 = relu(a0 @ W1 + b1) * rsqrt(deg_out1) ------
// 32 rows/block, 8 warps; warp w owns output cols [w*32, w*32+32)
#define TILE_R1 32
__global__ void __launch_bounds__(256) k_mm1(const float* __restrict__ b1) {
    __shared__ __half s_a[TILE_R1][EMB + 8];   // +8 pad: break 256B-stride bank collision
    __shared__ float s_sout[TILE_R1];
    int tid  = threadIdx.x;
    int wid  = tid >> 5;
    int lane = tid & 31;
    int row0 = blockIdx.x * TILE_R1;

    // stage A tile from global (coalesced)
#pragma unroll
    for (int r = wid; r < TILE_R1; r += 8) {
        uint2 v = *(const uint2*)(g_a0 + (size_t)(row0 + r) * EMB + lane * 4);
        *(uint2*)&s_a[r][lane * 4] = v;
    }
    if (tid < TILE_R1) s_sout[tid] = rsqrtf(fmaxf((float)g_deg_out1[row0 + tid], 1.0f));
    __syncthreads();

    // HMMA phase: m16n8k16.f32.f16.f16.f32, 2 m-tiles x 4 n-tiles per warp
    int n0 = wid * 32;
    int qr = lane >> 2;        // t/4
    int qc = (lane & 3) * 2;   // (t%4)*2
    float c[2][4][4];
#pragma unroll
    for (int m = 0; m < 2; m++)
#pragma unroll
        for (int nt = 0; nt < 4; nt++)
#pragma unroll
            for (int x = 0; x < 4; x++) c[m][nt][x] = 0.0f;

#pragma unroll
    for (int ks = 0; ks < 8; ks++) {
        int k0 = ks * 16;
        unsigned a[2][4];
#pragma unroll
        for (int m = 0; m < 2; m++) {
            int mr = m * 16 + qr;
            a[m][0] = *(const unsigned*)&s_a[mr][k0 + qc];
            a[m][1] = *(const unsigned*)&s_a[mr + 8][k0 + qc];
            a[m][2] = *(const unsigned*)&s_a[mr][k0 + qc + 8];
            a[m][3] = *(const unsigned*)&s_a[mr + 8][k0 + qc + 8];
        }
#pragma unroll
        for (int nt = 0; nt < 4; nt++) {
            int n = n0 + nt * 8 + qr;
            unsigned bb0 = *(const unsigned*)(g_w1t + (size_t)n * EMB + k0 + qc);
            unsigned bb1 = *(const unsigned*)(g_w1t + (size_t)n * EMB + k0 + qc + 8);
#pragma unroll
            for (int m = 0; m < 2; m++) {
                asm volatile(
                    "mma.sync.aligned.m16n8k16.row.col.f32.f16.f16.f32 "
                    "{%0,%1,%2,%3}, {%4,%5,%6,%7}, {%8,%9}, {%0,%1,%2,%3};"
                    : "+f"(c[m][nt][0]), "+f"(c[m][nt][1]),
                      "+f"(c[m][nt][2]), "+f"(c[m][nt][3])
                    : "r"(a[m][0]), "r"(a[m][1]), "r"(a[m][2]), "r"(a[m][3]),
                      "r"(bb0), "r"(bb1));
            }
        }
    }

    // epilogue: +bias, relu, *rsqrt(deg_out1), fp16 stores (half2 pairs)
#pragma unroll
    for (int nt = 0; nt < 4; nt++) {
        int col = n0 + nt * 8 + qc;
        float bc0 = b1[col], bc1 = b1[col + 1];
#pragma unroll
        for (int m = 0; m < 2; m++) {
            int rlo = m * 16 + qr, rhi = rlo + 8;
            float s0 = s_sout[rlo], s1 = s_sout[rhi];
            __half2 vlo = __floats2half2_rn(fmaxf(c[m][nt][0] + bc0, 0.0f) * s0,
                                            fmaxf(c[m][nt][1] + bc1, 0.0f) * s0);
            __half2 vhi = __floats2half2_rn(fmaxf(c[m][nt][2] + bc0, 0.0f) * s1,
                                            fmaxf(c[m][nt][3] + bc1, 0.0f) * s1);
            *(__half2*)&g_h16[(size_t)(row0 + rlo) * HID + col] = vlo;
            *(__half2*)&g_h16[(size_t)(row0 + rhi) * HID + col] = vhi;
        }
    }
}

// ---------------- layer-2 neighbor gather: one warp per dst row ----------------
// g_a1[row] = (sum_{s in ELL1[row]} h16[s]) * rsqrt(deg_in1[row])   (fp32 out)
__global__ void k_gather1(int n_rows) {
    int warp = (blockIdx.x * blockDim.x + threadIdx.x) >> 5;
    int lane = threadIdx.x & 31;
    if (warp >= n_rows) return;
    int deg = g_cnt1[warp];
    int dc  = deg < ST1 ? deg : ST1;
    const int* bkt = g_csr1 + (size_t)warp * ST1;
    const __half2 zero2 = __float2half2_rn(0.0f);
    __half2 acc[4] = {zero2, zero2, zero2, zero2};
    for (int j0 = 0; j0 < dc; j0 += 32) {
        int idx = (j0 + lane < dc) ? bkt[j0 + lane] : -1;
        int m = dc - j0; if (m > 32) m = 32;
#pragma unroll 8
        for (int jj = 0; jj < m; jj++) {
            int s = __shfl_sync(0xffffffffu, idx, jj);
            uint4 p = *(const uint4*)(g_h16 + (size_t)s * HID + lane * 8);
            acc[0] = __hadd2(acc[0], *(__half2*)&p.x);
            acc[1] = __hadd2(acc[1], *(__half2*)&p.y);
            acc[2] = __hadd2(acc[2], *(__half2*)&p.z);
            acc[3] = __hadd2(acc[3], *(__half2*)&p.w);
        }
    }
    float sc = rsqrtf(fmaxf((float)deg, 1.0f));
#pragma unroll
    for (int h = 0; h < 4; h++) {
        float2 f = __half22float2(acc[h]);
        float2 o; o.x = f.x * sc; o.y = f.y * sc;
        *(float2*)&g_a1[(size_t)warp * HID + lane * 8 + h * 2] = o;
    }
}

// ---------------- dense GEMM2: out = relu(a1 @ W2 + b2) -> d_out ----------------
__global__ void __launch_bounds__(256) k_mm2(const float* __restrict__ W2,
                                             const float* __restrict__ b2,
                                             float* __restrict__ out, int n_rows) {
    __shared__ float s_w[HID * OUTD];   // 16 KB
    __shared__ float s_a[16][HID];      // 16 KB
    int tid = threadIdx.x;
    int row0 = blockIdx.x * 16;

#pragma unroll
    for (int i = tid; i < HID * OUTD; i += 256) s_w[i] = W2[i];

    // stage A tile (16 rows x 256 floats), coalesced float4
#pragma unroll
    for (int i = tid; i < 16 * (HID / 4); i += 256) {
        int r = i / (HID / 4), k4 = i % (HID / 4);
        if (row0 + r < n_rows)
            *(float4*)&s_a[r][k4 * 4] = *(const float4*)&g_a1[(size_t)(row0 + r) * HID + k4 * 4];
    }
    __syncthreads();

    int r_local = tid >> 4;
    int c       = tid & 15;
    int row     = row0 + r_local;
    if (row >= n_rows) return;

    float acc = 0.0f;
#pragma unroll 8
    for (int k4 = 0; k4 < HID / 4; k4++) {
        float4 av = *(const float4*)&s_a[r_local][k4 * 4];
        acc = fmaf(av.x, s_w[(k4 * 4 + 0) * OUTD + c], acc);
        acc = fmaf(av.y, s_w[(k4 * 4 + 1) * OUTD + c], acc);
        acc = fmaf(av.z, s_w[(k4 * 4 + 2) * OUTD + c], acc);
        acc = fmaf(av.w, s_w[(k4 * 4 + 3) * OUTD + c], acc);
    }
    out[(size_t)row * OUTD + c] = fmaxf(acc + b2[c], 0.0f);
}

// ---------------- labels tail: cast int labels to float ----------------
__global__ void k_labels(const int* __restrict__ labels, float* __restrict__ out,
                         int offset, int n) {
    int i = blockIdx.x * blockDim.x + threadIdx.x;
    if (i < n) out[offset + i] = (float)labels[i];
}

extern "C" void kernel_launch(void* const* d_in, const int* in_sizes, int n_in,
                              void* d_out, int out_size) {
    const int*   user_word = (const int*)  d_in[0];
    const int*   labels    = (const int*)  d_in[1];
    const int*   src0      = (const int*)  d_in[2];
    const int*   dst0      = (const int*)  d_in[3];
    const int*   src1      = (const int*)  d_in[4];
    const int*   dst1      = (const int*)  d_in[5];
    const float* table     = (const float*)d_in[6];
    const float* W1        = (const float*)d_in[7];
    const float* b1        = (const float*)d_in[8];
    const float* W2        = (const float*)d_in[9];
    const float* b2        = (const float*)d_in[10];
    float* out = (float*)d_out;

    const int n_nodes = in_sizes[0] / WORDS_PER_NODE;  // 50000
    const int n_dst1  = in_sizes[1];                   // 5000
    const int e0      = in_sizes[2];                   // 300000
    const int e1      = in_sizes[4];                   // 75000

    // 1. init: fp16 table + fp16 W1^T + zero counters
    {
        size_t n4 = ((size_t)VOCAB * EMB) / 4;
        k_init<<<(unsigned)((n4 + 255) / 256), 256>>>(table, W1);
    }
    // 2. single edge pass: out-degrees + ELL buckets (cnt == in-degree)
    {
        int n = e0 > e1 ? e0 : e1;
        k_prep<<<(n + 1023) / 1024, 256>>>(src0, dst0, e0, src1, dst1, e1);
    }
    // 3. embedding gather/mean from fp16 table (+deg_out0 scale) -> fp16 x
    k_embed<<<(n_nodes * 32 + 255) / 256, 256>>>(user_word, n_nodes);
    // 4. layer-1 neighbor gather (warp per row, max parallelism)
    k_gather0<<<(N_DST0V * 32 + 255) / 256, 256>>>();
    // 5. dense HMMA GEMM1 -> fp16 h1
    k_mm1<<<N_DST0V / TILE_R1, 256>>>(b1);
    // 6. layer-2 neighbor gather
    k_gather1<<<(n_dst1 * 32 + 255) / 256, 256>>>(n_dst1);
    // 7. dense GEMM2 -> d_out head
    k_mm2<<<(n_dst1 + 15) / 16, 256>>>(W2, b2, out, n_dst1);
    // 8. labels tail (as float)
    int feat = n_dst1 * OUTD;
    int nlab = out_size - feat;
    if (nlab > 0) {
        if (nlab > n_dst1) nlab = n_dst1;
        k_labels<<<(nlab + 255) / 256, 256>>>(labels, out, feat, nlab);
    }
}